// round 5
// baseline (speedup 1.0000x reference)
#include <cuda_runtime.h>
#include <cuda_bf16.h>
#include <cstdint>

// ===========================================================================
// DAG-MLP via warp-level bf16 mma.sync (m16n8k16) — compute_103-safe.
// fp32 split into bf16 hi+lo; 3 MMA streams (hh + hl + lh) -> rel err ~3e-5.
// R5: 5-stage cp.async pipeline, incremental pointers (no div), single
// barrier per chunk, stream-major MMA order for ILP.
// ===========================================================================

#define BM 64
#define BN 64
#define BK 32
#define KSTR 40                        // padded K stride (bf16) = 80 B
#define TILE_B (64 * KSTR * 2)         // 5120 B
#define STAGE_B (4 * TILE_B)           // Ahi|Alo|Whi|Wlo = 20480 B
#define STAGES 5
#define GEMM_SMEM (STAGES * STAGE_B)   // 102400 B

// ---------------- scratch (device globals; no allocations) ----------------
__device__ __nv_bfloat16 g_Whi[15ll * 2048 * 2048];
__device__ __nv_bfloat16 g_Wlo[15ll * 2048 * 2048];
__device__ __nv_bfloat16 g_Ahi[6ll * 512 * 2048];
__device__ __nv_bfloat16 g_Alo[6ll * 512 * 2048];
__device__ __nv_bfloat16 g_xhi[512 * 800];
__device__ __nv_bfloat16 g_xlo[512 * 800];
__device__ __nv_bfloat16 g_winhi[2048 * 800];
__device__ __nv_bfloat16 g_winlo[2048 * 800];
__device__ float g_acts[6ll * 512 * 2048];

// ---------------- helpers ----------------
static __device__ __forceinline__ uint32_t smem_u32(const void* p) {
    uint32_t r;
    asm("{ .reg .u64 t; cvta.to.shared.u64 t, %1; cvt.u32.u64 %0, t; }"
        : "=r"(r) : "l"(p));
    return r;
}

static __device__ __forceinline__ uint32_t pack_bf2(__nv_bfloat16 a, __nv_bfloat16 b) {
    __nv_bfloat162 t; t.x = a; t.y = b;
    uint32_t u; memcpy(&u, &t, 4);
    return u;
}

static __device__ __forceinline__ void split1(float v, __nv_bfloat16& h, __nv_bfloat16& l) {
    h = __float2bfloat16(v);
    l = __float2bfloat16(v - __bfloat162float(h));
}

static __device__ __forceinline__ void cp16(uint32_t dst, const void* src) {
    asm volatile("cp.async.cg.shared.global [%0], [%1], 16;" :: "r"(dst), "l"(src));
}

static __device__ __forceinline__ void ldm4(uint32_t r[4], uint32_t addr) {
    asm volatile("ldmatrix.sync.aligned.m8n8.x4.shared.b16 {%0,%1,%2,%3}, [%4];"
                 : "=r"(r[0]), "=r"(r[1]), "=r"(r[2]), "=r"(r[3]) : "r"(addr));
}

static __device__ __forceinline__ void mma_bf16(
    float c[4], const uint32_t a[4], uint32_t b0, uint32_t b1) {
    asm volatile(
        "mma.sync.aligned.m16n8k16.row.col.f32.bf16.bf16.f32 "
        "{%0,%1,%2,%3}, {%4,%5,%6,%7}, {%8,%9}, {%0,%1,%2,%3};"
        : "+f"(c[0]), "+f"(c[1]), "+f"(c[2]), "+f"(c[3])
        : "r"(a[0]), "r"(a[1]), "r"(a[2]), "r"(a[3]), "r"(b0), "r"(b1));
}

// ---------------- pass 1: split kernels ----------------
__global__ void __launch_bounds__(256) split_wm_kernel(
    const float4* __restrict__ W, const float4* __restrict__ M,
    uint2* __restrict__ hi, uint2* __restrict__ lo, long long n4)
{
    long long i = (long long)blockIdx.x * 256 + threadIdx.x;
    if (i >= n4) return;
    const float4 w = W[i], m = M[i];
    float p0 = w.x * m.x, p1 = w.y * m.y, p2 = w.z * m.z, p3 = w.w * m.w;
    __nv_bfloat16 h0, h1, h2, h3, l0, l1, l2, l3;
    split1(p0, h0, l0); split1(p1, h1, l1); split1(p2, h2, l2); split1(p3, h3, l3);
    hi[i] = make_uint2(pack_bf2(h0, h1), pack_bf2(h2, h3));
    lo[i] = make_uint2(pack_bf2(l0, l1), pack_bf2(l2, l3));
}

__global__ void __launch_bounds__(256) split_pad_kernel(
    const float* __restrict__ src, int rows,
    __nv_bfloat16* __restrict__ hi, __nv_bfloat16* __restrict__ lo)
{
    long long i = (long long)blockIdx.x * 256 + threadIdx.x;
    if (i >= (long long)rows * 800) return;
    const int r = (int)(i / 800), c = (int)(i - (long long)r * 800);
    float v = (c < 784) ? src[(size_t)r * 784 + c] : 0.f;
    __nv_bfloat16 h, l;
    split1(v, h, l);
    hi[i] = h; lo[i] = l;
}

// ---------------- pass 2: GEMM layer kernel ----------------
__global__ void __launch_bounds__(256, 2) gemm_bf16_kernel(
    const __nv_bfloat16* __restrict__ Ahi, const __nv_bfloat16* __restrict__ Alo,
    int a_rs, long long a_ps,
    const __nv_bfloat16* __restrict__ Whi, const __nv_bfloat16* __restrict__ Wlo,
    int w_rs, long long w_ps,
    int npred, int Kdim,
    const float* __restrict__ bias, float bscale,
    float* __restrict__ outf,
    __nv_bfloat16* __restrict__ outh, __nv_bfloat16* __restrict__ outl)
{
    extern __shared__ char smem[];
    const uint32_t sb = smem_u32(smem);
    const int tid = threadIdx.x;
    const int wid = tid >> 5;
    const int lid = tid & 31;
    const int warp_m = wid >> 2;          // 0..1
    const int warp_n = wid & 3;           // 0..3
    const int gID = lid >> 2;             // 0..7
    const int tig = lid & 3;              // 0..3
    const int m_base = blockIdx.x * BM;
    const int n_base = blockIdx.y * BN;

    const int cpp   = Kdim >> 5;
    const int total = npred * cpp;        // always >= 25 here

    // cp.async mapping: 256 granules of 16B per 64x32 bf16 tile
    const int grow = tid >> 2;
    const int gcol = (tid & 3) * 8;
    const uint32_t sdst = sb + grow * (KSTR * 2) + (tid & 3) * 16;

    // incremental per-thread source pointers (no division in mainloop)
    const __nv_bfloat16* pAh = Ahi + (size_t)(m_base + grow) * a_rs + gcol;
    const __nv_bfloat16* pAl = Alo + (size_t)(m_base + grow) * a_rs + gcol;
    const __nv_bfloat16* pWh = Whi + (size_t)(n_base + grow) * w_rs + gcol;
    const __nv_bfloat16* pWl = Wlo + (size_t)(n_base + grow) * w_rs + gcol;
    const long long a_jump = a_ps - Kdim;
    const long long w_jump = w_ps - Kdim;
    int kcnt = cpp;
    uint32_t iss_off = 0;                 // issue stage byte offset

    auto issue_adv = [&]() {
        const uint32_t d = sdst + iss_off;
        cp16(d,              pAh);
        cp16(d + TILE_B,     pAl);
        cp16(d + 2 * TILE_B, pWh);
        cp16(d + 3 * TILE_B, pWl);
        pAh += BK; pAl += BK; pWh += BK; pWl += BK;
        if (--kcnt == 0) {
            kcnt = cpp;
            pAh += a_jump; pAl += a_jump; pWh += w_jump; pWl += w_jump;
        }
        iss_off += STAGE_B;
        if (iss_off == STAGES * STAGE_B) iss_off = 0;
    };

    float acc[2][2][4];
    #pragma unroll
    for (int mf = 0; mf < 2; ++mf)
        #pragma unroll
        for (int nf = 0; nf < 2; ++nf)
            #pragma unroll
            for (int e = 0; e < 4; ++e) acc[mf][nf][e] = 0.f;

    // ldmatrix lane addressing
    const int lrow  = lid & 15;
    const int khalf = (lid >> 4) * 8;
    const uint32_t aoff = ((warp_m * 32 + lrow) * KSTR + khalf) * 2;
    const uint32_t boff = ((warp_n * 16 + lrow) * KSTR + khalf) * 2 + 2 * TILE_B;

    // prologue: fill 4 stages
    #pragma unroll
    for (int p = 0; p < STAGES - 1; ++p) {
        issue_adv();
        asm volatile("cp.async.commit_group;");
    }

    uint32_t rd_off = 0;
    for (int g = 0; g < total; ++g) {
        asm volatile("cp.async.wait_group %0;" :: "n"(STAGES - 2));
        __syncthreads();
        if (g + STAGES - 1 < total) issue_adv();
        asm volatile("cp.async.commit_group;");

        const uint32_t st = sb + rd_off;
        rd_off += STAGE_B;
        if (rd_off == STAGES * STAGE_B) rd_off = 0;

        #pragma unroll
        for (int ks = 0; ks < 2; ++ks) {
            const uint32_t ko = ks * 32;
            uint32_t ah0[4], ah1[4], al0[4], al1[4], bh[4], bl[4];
            ldm4(bh, st + boff + ko);
            ldm4(bl, st + boff + TILE_B + ko);
            ldm4(ah0, st + aoff + ko);
            ldm4(ah1, st + aoff + 16 * KSTR * 2 + ko);
            ldm4(al0, st + aoff + TILE_B + ko);
            ldm4(al1, st + aoff + TILE_B + 16 * KSTR * 2 + ko);
            // stream-major: 4 independent accs between reuses
            mma_bf16(acc[0][0], ah0, bh[0], bh[2]);
            mma_bf16(acc[0][1], ah0, bh[1], bh[3]);
            mma_bf16(acc[1][0], ah1, bh[0], bh[2]);
            mma_bf16(acc[1][1], ah1, bh[1], bh[3]);
            mma_bf16(acc[0][0], ah0, bl[0], bl[2]);
            mma_bf16(acc[0][1], ah0, bl[1], bl[3]);
            mma_bf16(acc[1][0], ah1, bl[0], bl[2]);
            mma_bf16(acc[1][1], ah1, bl[1], bl[3]);
            mma_bf16(acc[0][0], al0, bh[0], bh[2]);
            mma_bf16(acc[0][1], al0, bh[1], bh[3]);
            mma_bf16(acc[1][0], al1, bh[0], bh[2]);
            mma_bf16(acc[1][1], al1, bh[1], bh[3]);
        }
    }

    // epilogue: bias + relu; write fp32 acts + pre-split bf16 acts
    #pragma unroll
    for (int mf = 0; mf < 2; ++mf) {
        const int r0 = m_base + warp_m * 32 + mf * 16 + gID;
        #pragma unroll
        for (int nf = 0; nf < 2; ++nf) {
            const int c0 = n_base + warp_n * 16 + nf * 8 + 2 * tig;
            const float bv0 = bscale * bias[c0];
            const float bv1 = bscale * bias[c0 + 1];
            const float v00 = fmaxf(acc[mf][nf][0] + bv0, 0.f);
            const float v01 = fmaxf(acc[mf][nf][1] + bv1, 0.f);
            const float v10 = fmaxf(acc[mf][nf][2] + bv0, 0.f);
            const float v11 = fmaxf(acc[mf][nf][3] + bv1, 0.f);
            const size_t o0 = (size_t)r0 * 2048 + c0;
            const size_t o1 = (size_t)(r0 + 8) * 2048 + c0;
            *(float2*)(outf + o0) = make_float2(v00, v01);
            *(float2*)(outf + o1) = make_float2(v10, v11);
            __nv_bfloat16 h0, h1, l0, l1;
            split1(v00, h0, l0); split1(v01, h1, l1);
            *(uint32_t*)(outh + o0) = pack_bf2(h0, h1);
            *(uint32_t*)(outl + o0) = pack_bf2(l0, l1);
            split1(v10, h0, l0); split1(v11, h1, l1);
            *(uint32_t*)(outh + o1) = pack_bf2(h0, h1);
            *(uint32_t*)(outl + o1) = pack_bf2(l0, l1);
        }
    }
}

// ---------------- output layer ----------------
__global__ void __launch_bounds__(256) output_kernel(
    const float* __restrict__ a5, const float* __restrict__ a4,
    const float* __restrict__ w1, const float* __restrict__ b1,
    const float* __restrict__ w2, const float* __restrict__ b2,
    float* __restrict__ out)
{
    __shared__ float red[10][257];
    const int brow = blockIdx.x;
    const int t = threadIdx.x;
    float s[10];
    #pragma unroll
    for (int c = 0; c < 10; ++c) s[c] = 0.f;
    const float* r5 = a5 + (size_t)brow * 2048;
    const float* r4 = a4 + (size_t)brow * 2048;
    for (int n = t; n < 2048; n += 256) {
        const float x5 = r5[n], x4 = r4[n];
        #pragma unroll
        for (int c = 0; c < 10; ++c)
            s[c] += x5 * w1[c * 2048 + n] + x4 * w2[c * 2048 + n];
    }
    #pragma unroll
    for (int c = 0; c < 10; ++c) red[c][t] = s[c];
    __syncthreads();
    for (int o = 128; o > 0; o >>= 1) {
        if (t < o) {
            #pragma unroll
            for (int c = 0; c < 10; ++c) red[c][t] += red[c][t + o];
        }
        __syncthreads();
    }
    if (t < 10) out[brow * 10 + t] = red[t][0] + b1[t] + b2[t];
}

// ---------------- kernel_launch ----------------
extern "C" void kernel_launch(void* const* d_in, const int* in_sizes, int n_in,
                              void* d_out, int out_size)
{
    const float* x   = (const float*)d_in[0];
    const float* win = (const float*)d_in[1];
    const float* bin = (const float*)d_in[2];
    const float* W   = (const float*)d_in[3];
    const float* Mm  = (const float*)d_in[4];
    const float* b   = (const float*)d_in[5];
    const float* w1  = (const float*)d_in[6];
    const float* b1  = (const float*)d_in[7];
    const float* w2  = (const float*)d_in[8];
    const float* b2  = (const float*)d_in[9];
    float* out = (float*)d_out;

    float *acts;
    __nv_bfloat16 *whi, *wlo, *ahi, *alo, *xhi, *xlo, *wihi, *wilo;
    cudaGetSymbolAddress((void**)&acts, g_acts);
    cudaGetSymbolAddress((void**)&whi, g_Whi);
    cudaGetSymbolAddress((void**)&wlo, g_Wlo);
    cudaGetSymbolAddress((void**)&ahi, g_Ahi);
    cudaGetSymbolAddress((void**)&alo, g_Alo);
    cudaGetSymbolAddress((void**)&xhi, g_xhi);
    cudaGetSymbolAddress((void**)&xlo, g_xlo);
    cudaGetSymbolAddress((void**)&wihi, g_winhi);
    cudaGetSymbolAddress((void**)&wilo, g_winlo);

    cudaFuncSetAttribute(gemm_bf16_kernel,
                         cudaFuncAttributeMaxDynamicSharedMemorySize, GEMM_SMEM);

    // pass 1: splits
    {
        const long long n4 = 15ll * 2048 * 2048 / 4;
        split_wm_kernel<<<(int)((n4 + 255) / 256), 256>>>(
            (const float4*)W, (const float4*)Mm, (uint2*)whi, (uint2*)wlo, n4);
        split_pad_kernel<<<(512 * 800 + 255) / 256, 256>>>(x, 512, xhi, xlo);
        split_pad_kernel<<<(2048 * 800 + 255) / 256, 256>>>(win, 2048, wihi, wilo);
    }

    const dim3 grid(512 / BM, 2048 / BN);   // 8 x 32 = 256 CTAs
    const dim3 blk(256);

    // layer 0: act0 = relu(x @ w_in^T + b_in), padded K=800
    gemm_bf16_kernel<<<grid, blk, GEMM_SMEM>>>(
        xhi, xlo, 800, 0LL, wihi, wilo, 800, 0LL, 1, 800,
        bin, 1.0f, acts, ahi, alo);

    // DAG layers 1..5
    long long idx = 0;
    for (int i = 1; i < 6; ++i) {
        gemm_bf16_kernel<<<grid, blk, GEMM_SMEM>>>(
            ahi, alo, 2048, 512LL * 2048,
            whi + idx * 2048 * 2048, wlo + idx * 2048 * 2048,
            2048, 2048LL * 2048,
            i, 2048,
            b + (size_t)(i - 1) * 2048, (float)i,
            acts + (size_t)i * 512 * 2048,
            ahi + (size_t)i * 512 * 2048,
            alo + (size_t)i * 512 * 2048);
        idx += i;
    }

    output_kernel<<<512, 256>>>(
        acts + 5LL * 512 * 2048, acts + 4LL * 512 * 2048,
        w1, b1, w2, b2, out);
}

// round 6
// speedup vs baseline: 1.0019x; 1.0019x over previous
#include <cuda_runtime.h>
#include <cuda_bf16.h>
#include <cstdint>

// ===========================================================================
// DAG-MLP via warp-level bf16 mma.sync (m16n8k16) — compute_103-safe.
// fp32 split into bf16 hi+lo; 3 MMA streams (hh + hl + lh) -> rel err ~3e-5.
// R6: 3-stage pipeline @ 3 CTAs/SM, split_wm chunked for overlap-free
// measurement (ncu slot 6) and 8-elem/thread vectorization.
// ===========================================================================

#define BM 64
#define BN 64
#define BK 32
#define KSTR 40                        // padded K stride (bf16) = 80 B
#define TILE_B (64 * KSTR * 2)         // 5120 B
#define STAGE_B (4 * TILE_B)           // Ahi|Alo|Whi|Wlo = 20480 B
#define STAGES 3
#define GEMM_SMEM (STAGES * STAGE_B)   // 61440 B -> 3 CTAs/SM

// ---------------- scratch (device globals; no allocations) ----------------
__device__ __nv_bfloat16 g_Whi[15ll * 2048 * 2048];
__device__ __nv_bfloat16 g_Wlo[15ll * 2048 * 2048];
__device__ __nv_bfloat16 g_Ahi[6ll * 512 * 2048];
__device__ __nv_bfloat16 g_Alo[6ll * 512 * 2048];
__device__ __nv_bfloat16 g_xhi[512 * 800];
__device__ __nv_bfloat16 g_xlo[512 * 800];
__device__ __nv_bfloat16 g_winhi[2048 * 800];
__device__ __nv_bfloat16 g_winlo[2048 * 800];
__device__ float g_acts[6ll * 512 * 2048];

// ---------------- helpers ----------------
static __device__ __forceinline__ uint32_t smem_u32(const void* p) {
    uint32_t r;
    asm("{ .reg .u64 t; cvta.to.shared.u64 t, %1; cvt.u32.u64 %0, t; }"
        : "=r"(r) : "l"(p));
    return r;
}

static __device__ __forceinline__ uint32_t pack_bf2(__nv_bfloat16 a, __nv_bfloat16 b) {
    __nv_bfloat162 t; t.x = a; t.y = b;
    uint32_t u; memcpy(&u, &t, 4);
    return u;
}

static __device__ __forceinline__ void split1(float v, __nv_bfloat16& h, __nv_bfloat16& l) {
    h = __float2bfloat16(v);
    l = __float2bfloat16(v - __bfloat162float(h));
}

static __device__ __forceinline__ void cp16(uint32_t dst, const void* src) {
    asm volatile("cp.async.cg.shared.global [%0], [%1], 16;" :: "r"(dst), "l"(src));
}

static __device__ __forceinline__ void ldm4(uint32_t r[4], uint32_t addr) {
    asm volatile("ldmatrix.sync.aligned.m8n8.x4.shared.b16 {%0,%1,%2,%3}, [%4];"
                 : "=r"(r[0]), "=r"(r[1]), "=r"(r[2]), "=r"(r[3]) : "r"(addr));
}

static __device__ __forceinline__ void mma_bf16(
    float c[4], const uint32_t a[4], uint32_t b0, uint32_t b1) {
    asm volatile(
        "mma.sync.aligned.m16n8k16.row.col.f32.bf16.bf16.f32 "
        "{%0,%1,%2,%3}, {%4,%5,%6,%7}, {%8,%9}, {%0,%1,%2,%3};"
        : "+f"(c[0]), "+f"(c[1]), "+f"(c[2]), "+f"(c[3])
        : "r"(a[0]), "r"(a[1]), "r"(a[2]), "r"(a[3]), "r"(b0), "r"(b1));
}

// ---------------- pass 1: split kernels ----------------
// 8 elems/thread: 2x float4 loads per array, 1x uint4 store per array.
__global__ void __launch_bounds__(256) split_wm_kernel(
    const float4* __restrict__ W, const float4* __restrict__ M,
    uint4* __restrict__ hi, uint4* __restrict__ lo, long long n8)
{
    long long i = (long long)blockIdx.x * 256 + threadIdx.x;
    if (i >= n8) return;
    const float4 w0 = W[2 * i], w1 = W[2 * i + 1];
    const float4 m0 = M[2 * i], m1 = M[2 * i + 1];
    float p[8] = { w0.x * m0.x, w0.y * m0.y, w0.z * m0.z, w0.w * m0.w,
                   w1.x * m1.x, w1.y * m1.y, w1.z * m1.z, w1.w * m1.w };
    __nv_bfloat16 h[8], l[8];
    #pragma unroll
    for (int e = 0; e < 8; ++e) split1(p[e], h[e], l[e]);
    hi[i] = make_uint4(pack_bf2(h[0], h[1]), pack_bf2(h[2], h[3]),
                       pack_bf2(h[4], h[5]), pack_bf2(h[6], h[7]));
    lo[i] = make_uint4(pack_bf2(l[0], l[1]), pack_bf2(l[2], l[3]),
                       pack_bf2(l[4], l[5]), pack_bf2(l[6], l[7]));
}

__global__ void __launch_bounds__(256) split_pad_kernel(
    const float* __restrict__ src, int rows,
    __nv_bfloat16* __restrict__ hi, __nv_bfloat16* __restrict__ lo)
{
    long long i = (long long)blockIdx.x * 256 + threadIdx.x;
    if (i >= (long long)rows * 800) return;
    const int r = (int)(i / 800), c = (int)(i - (long long)r * 800);
    float v = (c < 784) ? src[(size_t)r * 784 + c] : 0.f;
    __nv_bfloat16 h, l;
    split1(v, h, l);
    hi[i] = h; lo[i] = l;
}

// ---------------- pass 2: GEMM layer kernel ----------------
__global__ void __launch_bounds__(256, 3) gemm_bf16_kernel(
    const __nv_bfloat16* __restrict__ Ahi, const __nv_bfloat16* __restrict__ Alo,
    int a_rs, long long a_ps,
    const __nv_bfloat16* __restrict__ Whi, const __nv_bfloat16* __restrict__ Wlo,
    int w_rs, long long w_ps,
    int npred, int Kdim,
    const float* __restrict__ bias, float bscale,
    float* __restrict__ outf,
    __nv_bfloat16* __restrict__ outh, __nv_bfloat16* __restrict__ outl)
{
    extern __shared__ char smem[];
    const uint32_t sb = smem_u32(smem);
    const int tid = threadIdx.x;
    const int wid = tid >> 5;
    const int lid = tid & 31;
    const int warp_m = wid >> 2;          // 0..1
    const int warp_n = wid & 3;           // 0..3
    const int gID = lid >> 2;             // 0..7
    const int tig = lid & 3;              // 0..3
    const int m_base = blockIdx.x * BM;
    const int n_base = blockIdx.y * BN;

    const int cpp   = Kdim >> 5;
    const int total = npred * cpp;

    // cp.async mapping: 256 granules of 16B per 64x32 bf16 tile
    const int grow = tid >> 2;
    const int gcol = (tid & 3) * 8;
    const uint32_t sdst = sb + grow * (KSTR * 2) + (tid & 3) * 16;

    // incremental per-thread source pointers
    const __nv_bfloat16* pAh = Ahi + (size_t)(m_base + grow) * a_rs + gcol;
    const __nv_bfloat16* pAl = Alo + (size_t)(m_base + grow) * a_rs + gcol;
    const __nv_bfloat16* pWh = Whi + (size_t)(n_base + grow) * w_rs + gcol;
    const __nv_bfloat16* pWl = Wlo + (size_t)(n_base + grow) * w_rs + gcol;
    const long long a_jump = a_ps - Kdim;
    const long long w_jump = w_ps - Kdim;
    int kcnt = cpp;
    uint32_t iss_off = 0;

    auto issue_adv = [&]() {
        const uint32_t d = sdst + iss_off;
        cp16(d,              pAh);
        cp16(d + TILE_B,     pAl);
        cp16(d + 2 * TILE_B, pWh);
        cp16(d + 3 * TILE_B, pWl);
        pAh += BK; pAl += BK; pWh += BK; pWl += BK;
        if (--kcnt == 0) {
            kcnt = cpp;
            pAh += a_jump; pAl += a_jump; pWh += w_jump; pWl += w_jump;
        }
        iss_off += STAGE_B;
        if (iss_off == STAGES * STAGE_B) iss_off = 0;
    };

    float acc[2][2][4];
    #pragma unroll
    for (int mf = 0; mf < 2; ++mf)
        #pragma unroll
        for (int nf = 0; nf < 2; ++nf)
            #pragma unroll
            for (int e = 0; e < 4; ++e) acc[mf][nf][e] = 0.f;

    // ldmatrix lane addressing
    const int lrow  = lid & 15;
    const int khalf = (lid >> 4) * 8;
    const uint32_t aoff = ((warp_m * 32 + lrow) * KSTR + khalf) * 2;
    const uint32_t boff = ((warp_n * 16 + lrow) * KSTR + khalf) * 2 + 2 * TILE_B;

    // prologue: fill STAGES-1 stages
    #pragma unroll
    for (int p = 0; p < STAGES - 1; ++p) {
        issue_adv();
        asm volatile("cp.async.commit_group;");
    }

    uint32_t rd_off = 0;
    for (int g = 0; g < total; ++g) {
        asm volatile("cp.async.wait_group %0;" :: "n"(STAGES - 2));
        __syncthreads();
        if (g + STAGES - 1 < total) issue_adv();
        asm volatile("cp.async.commit_group;");

        const uint32_t st = sb + rd_off;
        rd_off += STAGE_B;
        if (rd_off == STAGES * STAGE_B) rd_off = 0;

        #pragma unroll
        for (int ks = 0; ks < 2; ++ks) {
            const uint32_t ko = ks * 32;
            uint32_t ah0[4], ah1[4], al0[4], al1[4], bh[4], bl[4];
            ldm4(bh, st + boff + ko);
            ldm4(bl, st + boff + TILE_B + ko);
            ldm4(ah0, st + aoff + ko);
            ldm4(ah1, st + aoff + 16 * KSTR * 2 + ko);
            ldm4(al0, st + aoff + TILE_B + ko);
            ldm4(al1, st + aoff + TILE_B + 16 * KSTR * 2 + ko);
            mma_bf16(acc[0][0], ah0, bh[0], bh[2]);
            mma_bf16(acc[0][1], ah0, bh[1], bh[3]);
            mma_bf16(acc[1][0], ah1, bh[0], bh[2]);
            mma_bf16(acc[1][1], ah1, bh[1], bh[3]);
            mma_bf16(acc[0][0], ah0, bl[0], bl[2]);
            mma_bf16(acc[0][1], ah0, bl[1], bl[3]);
            mma_bf16(acc[1][0], ah1, bl[0], bl[2]);
            mma_bf16(acc[1][1], ah1, bl[1], bl[3]);
            mma_bf16(acc[0][0], al0, bh[0], bh[2]);
            mma_bf16(acc[0][1], al0, bh[1], bh[3]);
            mma_bf16(acc[1][0], al1, bh[0], bh[2]);
            mma_bf16(acc[1][1], al1, bh[1], bh[3]);
        }
    }

    // epilogue: bias + relu; write fp32 acts + pre-split bf16 acts
    #pragma unroll
    for (int mf = 0; mf < 2; ++mf) {
        const int r0 = m_base + warp_m * 32 + mf * 16 + gID;
        #pragma unroll
        for (int nf = 0; nf < 2; ++nf) {
            const int c0 = n_base + warp_n * 16 + nf * 8 + 2 * tig;
            const float bv0 = bscale * bias[c0];
            const float bv1 = bscale * bias[c0 + 1];
            const float v00 = fmaxf(acc[mf][nf][0] + bv0, 0.f);
            const float v01 = fmaxf(acc[mf][nf][1] + bv1, 0.f);
            const float v10 = fmaxf(acc[mf][nf][2] + bv0, 0.f);
            const float v11 = fmaxf(acc[mf][nf][3] + bv1, 0.f);
            const size_t o0 = (size_t)r0 * 2048 + c0;
            const size_t o1 = (size_t)(r0 + 8) * 2048 + c0;
            *(float2*)(outf + o0) = make_float2(v00, v01);
            *(float2*)(outf + o1) = make_float2(v10, v11);
            __nv_bfloat16 h0, h1, l0, l1;
            split1(v00, h0, l0); split1(v01, h1, l1);
            *(uint32_t*)(outh + o0) = pack_bf2(h0, h1);
            *(uint32_t*)(outl + o0) = pack_bf2(l0, l1);
            split1(v10, h0, l0); split1(v11, h1, l1);
            *(uint32_t*)(outh + o1) = pack_bf2(h0, h1);
            *(uint32_t*)(outl + o1) = pack_bf2(l0, l1);
        }
    }
}

// ---------------- output layer ----------------
__global__ void __launch_bounds__(256) output_kernel(
    const float* __restrict__ a5, const float* __restrict__ a4,
    const float* __restrict__ w1, const float* __restrict__ b1,
    const float* __restrict__ w2, const float* __restrict__ b2,
    float* __restrict__ out)
{
    __shared__ float red[10][257];
    const int brow = blockIdx.x;
    const int t = threadIdx.x;
    float s[10];
    #pragma unroll
    for (int c = 0; c < 10; ++c) s[c] = 0.f;
    const float* r5 = a5 + (size_t)brow * 2048;
    const float* r4 = a4 + (size_t)brow * 2048;
    for (int n = t; n < 2048; n += 256) {
        const float x5 = r5[n], x4 = r4[n];
        #pragma unroll
        for (int c = 0; c < 10; ++c)
            s[c] += x5 * w1[c * 2048 + n] + x4 * w2[c * 2048 + n];
    }
    #pragma unroll
    for (int c = 0; c < 10; ++c) red[c][t] = s[c];
    __syncthreads();
    for (int o = 128; o > 0; o >>= 1) {
        if (t < o) {
            #pragma unroll
            for (int c = 0; c < 10; ++c) red[c][t] += red[c][t + o];
        }
        __syncthreads();
    }
    if (t < 10) out[brow * 10 + t] = red[t][0] + b1[t] + b2[t];
}

// ---------------- kernel_launch ----------------
extern "C" void kernel_launch(void* const* d_in, const int* in_sizes, int n_in,
                              void* d_out, int out_size)
{
    const float* x   = (const float*)d_in[0];
    const float* win = (const float*)d_in[1];
    const float* bin = (const float*)d_in[2];
    const float* W   = (const float*)d_in[3];
    const float* Mm  = (const float*)d_in[4];
    const float* b   = (const float*)d_in[5];
    const float* w1  = (const float*)d_in[6];
    const float* b1  = (const float*)d_in[7];
    const float* w2  = (const float*)d_in[8];
    const float* b2  = (const float*)d_in[9];
    float* out = (float*)d_out;

    float *acts;
    __nv_bfloat16 *whi, *wlo, *ahi, *alo, *xhi, *xlo, *wihi, *wilo;
    cudaGetSymbolAddress((void**)&acts, g_acts);
    cudaGetSymbolAddress((void**)&whi, g_Whi);
    cudaGetSymbolAddress((void**)&wlo, g_Wlo);
    cudaGetSymbolAddress((void**)&ahi, g_Ahi);
    cudaGetSymbolAddress((void**)&alo, g_Alo);
    cudaGetSymbolAddress((void**)&xhi, g_xhi);
    cudaGetSymbolAddress((void**)&xlo, g_xlo);
    cudaGetSymbolAddress((void**)&wihi, g_winhi);
    cudaGetSymbolAddress((void**)&wilo, g_winlo);

    cudaFuncSetAttribute(gemm_bf16_kernel,
                         cudaFuncAttributeMaxDynamicSharedMemorySize, GEMM_SMEM);

    const dim3 grid(512 / BM, 2048 / BN);   // 8 x 32 = 256 CTAs
    const dim3 blk(256);

    // (1,2) input splits
    split_pad_kernel<<<(512 * 800 + 255) / 256, 256>>>(x, 512, xhi, xlo);
    split_pad_kernel<<<(2048 * 800 + 255) / 256, 256>>>(win, 2048, wihi, wilo);

    // (3) layer 0: act0 = relu(x @ w_in^T + b_in), padded K=800
    gemm_bf16_kernel<<<grid, blk, GEMM_SMEM>>>(
        xhi, xlo, 800, 0LL, wihi, wilo, 800, 0LL, 1, 800,
        bin, 1.0f, acts, ahi, alo);

    // (4) split W*M part A: matrices 0..5 (layers 1-3)
    {
        const long long n8 = 6ll * 2048 * 2048 / 8;
        split_wm_kernel<<<(int)((n8 + 255) / 256), 256>>>(
            (const float4*)W, (const float4*)Mm, (uint4*)whi, (uint4*)wlo, n8);
    }

    // (5) layer 1
    gemm_bf16_kernel<<<grid, blk, GEMM_SMEM>>>(
        ahi, alo, 2048, 512LL * 2048,
        whi, wlo, 2048, 2048LL * 2048, 1, 2048,
        b, 1.0f, acts + 512LL * 2048, ahi + 512LL * 2048, alo + 512LL * 2048);

    // (6) split W*M part B: matrices 6..14 (layers 4-5)  <- ncu capture slot
    {
        const long long off = 6ll * 2048 * 2048;
        const long long n8 = 9ll * 2048 * 2048 / 8;
        split_wm_kernel<<<(int)((n8 + 255) / 256), 256>>>(
            (const float4*)(W + off), (const float4*)(Mm + off),
            (uint4*)(whi + off), (uint4*)(wlo + off), n8);
    }

    // (7..10) layers 2..5
    long long idx = 1;
    for (int i = 2; i < 6; ++i) {
        gemm_bf16_kernel<<<grid, blk, GEMM_SMEM>>>(
            ahi, alo, 2048, 512LL * 2048,
            whi + idx * 2048 * 2048, wlo + idx * 2048 * 2048,
            2048, 2048LL * 2048,
            i, 2048,
            b + (size_t)(i - 1) * 2048, (float)i,
            acts + (size_t)i * 512 * 2048,
            ahi + (size_t)i * 512 * 2048,
            alo + (size_t)i * 512 * 2048);
        idx += i;
    }

    // (11) output layer
    output_kernel<<<512, 256>>>(
        acts + 5LL * 512 * 2048, acts + 4LL * 512 * 2048,
        w1, b1, w2, b2, out);
}

// round 7
// speedup vs baseline: 1.2088x; 1.2065x over previous
#include <cuda_runtime.h>
#include <cuda_bf16.h>
#include <cstdint>

// ===========================================================================
// DAG-MLP via warp-level bf16 mma.sync (m16n8k16) — compute_103-safe.
// fp32 split into bf16 hi+lo; 3 MMA streams (hh + hl + lh) -> rel err ~3e-5.
// R7: 128x128 tiles (512 thr, 16 warps), split-K=2, 4-stage cp.async.
// Rationale: 64x64 tiles were L2-BW-bound (19 MAC/B, ~5.2GB L2 traffic);
// 128x128 gives 49 MAC/B (~2.0GB).
// ===========================================================================

#define BM 128
#define BN 128
#define BK 32
#define KSTR 40                        // padded K stride (bf16) = 80 B
#define TILE_B (128 * KSTR * 2)        // 10240 B
#define STAGE_B (4 * TILE_B)           // Ahi|Alo|Whi|Wlo = 40960 B
#define STAGES 4
#define GEMM_SMEM (STAGES * STAGE_B)   // 163840 B

// ---------------- scratch (device globals; no allocations) ----------------
__device__ __nv_bfloat16 g_Whi[15ll * 2048 * 2048];
__device__ __nv_bfloat16 g_Wlo[15ll * 2048 * 2048];
__device__ __nv_bfloat16 g_Ahi[6ll * 512 * 2048];
__device__ __nv_bfloat16 g_Alo[6ll * 512 * 2048];
__device__ __nv_bfloat16 g_xhi[512 * 800];
__device__ __nv_bfloat16 g_xlo[512 * 800];
__device__ __nv_bfloat16 g_winhi[2048 * 800];
__device__ __nv_bfloat16 g_winlo[2048 * 800];
__device__ float g_acts[6ll * 512 * 2048];
__device__ float g_part[2ll * 512 * 2048];   // split-K partials

// ---------------- helpers ----------------
static __device__ __forceinline__ uint32_t smem_u32(const void* p) {
    uint32_t r;
    asm("{ .reg .u64 t; cvta.to.shared.u64 t, %1; cvt.u32.u64 %0, t; }"
        : "=r"(r) : "l"(p));
    return r;
}

static __device__ __forceinline__ uint32_t pack_bf2(__nv_bfloat16 a, __nv_bfloat16 b) {
    __nv_bfloat162 t; t.x = a; t.y = b;
    uint32_t u; memcpy(&u, &t, 4);
    return u;
}

static __device__ __forceinline__ void split1(float v, __nv_bfloat16& h, __nv_bfloat16& l) {
    h = __float2bfloat16(v);
    l = __float2bfloat16(v - __bfloat162float(h));
}

static __device__ __forceinline__ void cp16(uint32_t dst, const void* src) {
    asm volatile("cp.async.cg.shared.global [%0], [%1], 16;" :: "r"(dst), "l"(src));
}

static __device__ __forceinline__ void ldm4(uint32_t r[4], uint32_t addr) {
    asm volatile("ldmatrix.sync.aligned.m8n8.x4.shared.b16 {%0,%1,%2,%3}, [%4];"
                 : "=r"(r[0]), "=r"(r[1]), "=r"(r[2]), "=r"(r[3]) : "r"(addr));
}

static __device__ __forceinline__ void mma_bf16(
    float c[4], const uint32_t a[4], uint32_t b0, uint32_t b1) {
    asm volatile(
        "mma.sync.aligned.m16n8k16.row.col.f32.bf16.bf16.f32 "
        "{%0,%1,%2,%3}, {%4,%5,%6,%7}, {%8,%9}, {%0,%1,%2,%3};"
        : "+f"(c[0]), "+f"(c[1]), "+f"(c[2]), "+f"(c[3])
        : "r"(a[0]), "r"(a[1]), "r"(a[2]), "r"(a[3]), "r"(b0), "r"(b1));
}

// ---------------- pass 1: split kernels ----------------
__global__ void __launch_bounds__(256) split_wm_kernel(
    const float4* __restrict__ W, const float4* __restrict__ M,
    uint4* __restrict__ hi, uint4* __restrict__ lo, long long n8)
{
    long long i = (long long)blockIdx.x * 256 + threadIdx.x;
    if (i >= n8) return;
    const float4 w0 = W[2 * i], w1 = W[2 * i + 1];
    const float4 m0 = M[2 * i], m1 = M[2 * i + 1];
    float p[8] = { w0.x * m0.x, w0.y * m0.y, w0.z * m0.z, w0.w * m0.w,
                   w1.x * m1.x, w1.y * m1.y, w1.z * m1.z, w1.w * m1.w };
    __nv_bfloat16 h[8], l[8];
    #pragma unroll
    for (int e = 0; e < 8; ++e) split1(p[e], h[e], l[e]);
    hi[i] = make_uint4(pack_bf2(h[0], h[1]), pack_bf2(h[2], h[3]),
                       pack_bf2(h[4], h[5]), pack_bf2(h[6], h[7]));
    lo[i] = make_uint4(pack_bf2(l[0], l[1]), pack_bf2(l[2], l[3]),
                       pack_bf2(l[4], l[5]), pack_bf2(l[6], l[7]));
}

__global__ void __launch_bounds__(256) split_pad_kernel(
    const float* __restrict__ src, int rows,
    __nv_bfloat16* __restrict__ hi, __nv_bfloat16* __restrict__ lo)
{
    long long i = (long long)blockIdx.x * 256 + threadIdx.x;
    if (i >= (long long)rows * 800) return;
    const int r = (int)(i / 800), c = (int)(i - (long long)r * 800);
    float v = (c < 784) ? src[(size_t)r * 784 + c] : 0.f;
    __nv_bfloat16 h, l;
    split1(v, h, l);
    hi[i] = h; lo[i] = l;
}

// ---------------- pass 2: GEMM layer kernel (split-K partial) --------------
//   part[z][m,n] = sum over this z's K-chunks of A_j[m,k]*W_j[n,k] (3 streams)
__global__ void __launch_bounds__(512, 1) gemm_bf16_kernel(
    const __nv_bfloat16* __restrict__ Ahi, const __nv_bfloat16* __restrict__ Alo,
    int a_rs, long long a_ps,
    const __nv_bfloat16* __restrict__ Whi, const __nv_bfloat16* __restrict__ Wlo,
    int w_rs, long long w_ps,
    int npred, int Kdim,
    float* __restrict__ part)
{
    extern __shared__ char smem[];
    const uint32_t sb = smem_u32(smem);
    const int tid = threadIdx.x;
    const int wid = tid >> 5;
    const int lid = tid & 31;
    const int warp_m = wid >> 2;          // 0..3
    const int warp_n = wid & 3;           // 0..3
    const int gID = lid >> 2;             // 0..7
    const int tig = lid & 3;              // 0..3
    const int m_base = blockIdx.x * BM;
    const int n_base = blockIdx.y * BN;

    const int cpp   = Kdim >> 5;
    const int total = npred * cpp;
    const int half  = (total + 1) >> 1;
    const int g_begin = blockIdx.z ? half : 0;
    const int my_n    = blockIdx.z ? (total - half) : half;

    // cp.async mapping: 512 granules of 16B per 128x32 bf16 tile
    const int grow = tid >> 2;            // 0..127
    const int gcol = (tid & 3) * 8;
    const uint32_t sdst = sb + grow * (KSTR * 2) + (tid & 3) * 16;

    // per-thread source pointers starting at chunk g_begin
    const int j0   = g_begin / cpp;
    const int krem = g_begin - j0 * cpp;
    const __nv_bfloat16* pAh = Ahi + (size_t)j0 * a_ps + (size_t)(m_base + grow) * a_rs + krem * BK + gcol;
    const __nv_bfloat16* pAl = Alo + (size_t)j0 * a_ps + (size_t)(m_base + grow) * a_rs + krem * BK + gcol;
    const __nv_bfloat16* pWh = Whi + (size_t)j0 * w_ps + (size_t)(n_base + grow) * w_rs + krem * BK + gcol;
    const __nv_bfloat16* pWl = Wlo + (size_t)j0 * w_ps + (size_t)(n_base + grow) * w_rs + krem * BK + gcol;
    const long long a_jump = a_ps - Kdim;
    const long long w_jump = w_ps - Kdim;
    int kcnt = cpp - krem;
    uint32_t iss_off = 0;

    auto issue_adv = [&]() {
        const uint32_t d = sdst + iss_off;
        cp16(d,              pAh);
        cp16(d + TILE_B,     pAl);
        cp16(d + 2 * TILE_B, pWh);
        cp16(d + 3 * TILE_B, pWl);
        pAh += BK; pAl += BK; pWh += BK; pWl += BK;
        if (--kcnt == 0) {
            kcnt = cpp;
            pAh += a_jump; pAl += a_jump; pWh += w_jump; pWl += w_jump;
        }
        iss_off += STAGE_B;
        if (iss_off == STAGES * STAGE_B) iss_off = 0;
    };

    float acc[2][4][4];
    #pragma unroll
    for (int mf = 0; mf < 2; ++mf)
        #pragma unroll
        for (int nf = 0; nf < 4; ++nf)
            #pragma unroll
            for (int e = 0; e < 4; ++e) acc[mf][nf][e] = 0.f;

    // ldmatrix lane addressing
    const int lrow  = lid & 15;
    const int khalf = (lid >> 4) * 8;
    const uint32_t aoff  = ((warp_m * 32 + lrow) * KSTR + khalf) * 2;
    const uint32_t boff0 = ((warp_n * 32 + lrow) * KSTR + khalf) * 2 + 2 * TILE_B;
    const uint32_t boff1 = boff0 + 16 * KSTR * 2;

    #pragma unroll
    for (int p = 0; p < STAGES - 1; ++p) {
        if (p < my_n) issue_adv();
        asm volatile("cp.async.commit_group;");
    }

    uint32_t rd_off = 0;
    for (int g = 0; g < my_n; ++g) {
        asm volatile("cp.async.wait_group %0;" :: "n"(STAGES - 2));
        __syncthreads();
        if (g + STAGES - 1 < my_n) issue_adv();
        asm volatile("cp.async.commit_group;");

        const uint32_t st = sb + rd_off;
        rd_off += STAGE_B;
        if (rd_off == STAGES * STAGE_B) rd_off = 0;

        #pragma unroll
        for (int ks = 0; ks < 2; ++ks) {
            const uint32_t ko = ks * 32;
            uint32_t ah0[4], ah1[4], al0[4], al1[4];
            uint32_t bh0[4], bh1[4], bl0[4], bl1[4];
            ldm4(bh0, st + boff0 + ko);
            ldm4(bh1, st + boff1 + ko);
            ldm4(bl0, st + boff0 + TILE_B + ko);
            ldm4(bl1, st + boff1 + TILE_B + ko);
            ldm4(ah0, st + aoff + ko);
            ldm4(ah1, st + aoff + 16 * KSTR * 2 + ko);
            ldm4(al0, st + aoff + TILE_B + ko);
            ldm4(al1, st + aoff + TILE_B + 16 * KSTR * 2 + ko);
            // hh stream (8 independent)
            mma_bf16(acc[0][0], ah0, bh0[0], bh0[2]);
            mma_bf16(acc[0][1], ah0, bh0[1], bh0[3]);
            mma_bf16(acc[0][2], ah0, bh1[0], bh1[2]);
            mma_bf16(acc[0][3], ah0, bh1[1], bh1[3]);
            mma_bf16(acc[1][0], ah1, bh0[0], bh0[2]);
            mma_bf16(acc[1][1], ah1, bh0[1], bh0[3]);
            mma_bf16(acc[1][2], ah1, bh1[0], bh1[2]);
            mma_bf16(acc[1][3], ah1, bh1[1], bh1[3]);
            // hl stream
            mma_bf16(acc[0][0], ah0, bl0[0], bl0[2]);
            mma_bf16(acc[0][1], ah0, bl0[1], bl0[3]);
            mma_bf16(acc[0][2], ah0, bl1[0], bl1[2]);
            mma_bf16(acc[0][3], ah0, bl1[1], bl1[3]);
            mma_bf16(acc[1][0], ah1, bl0[0], bl0[2]);
            mma_bf16(acc[1][1], ah1, bl0[1], bl0[3]);
            mma_bf16(acc[1][2], ah1, bl1[0], bl1[2]);
            mma_bf16(acc[1][3], ah1, bl1[1], bl1[3]);
            // lh stream
            mma_bf16(acc[0][0], al0, bh0[0], bh0[2]);
            mma_bf16(acc[0][1], al0, bh0[1], bh0[3]);
            mma_bf16(acc[0][2], al0, bh1[0], bh1[2]);
            mma_bf16(acc[0][3], al0, bh1[1], bh1[3]);
            mma_bf16(acc[1][0], al1, bh0[0], bh0[2]);
            mma_bf16(acc[1][1], al1, bh0[1], bh0[3]);
            mma_bf16(acc[1][2], al1, bh1[0], bh1[2]);
            mma_bf16(acc[1][3], al1, bh1[1], bh1[3]);
        }
    }

    // store split-K partials (fp32, no bias)
    float* pz = part + (size_t)blockIdx.z * 512 * 2048;
    #pragma unroll
    for (int mf = 0; mf < 2; ++mf) {
        const int r0 = m_base + warp_m * 32 + mf * 16 + gID;
        #pragma unroll
        for (int nf = 0; nf < 4; ++nf) {
            const int c0 = n_base + warp_n * 32 + nf * 8 + 2 * tig;
            *(float2*)(pz + (size_t)r0 * 2048 + c0)       = make_float2(acc[mf][nf][0], acc[mf][nf][1]);
            *(float2*)(pz + (size_t)(r0 + 8) * 2048 + c0) = make_float2(acc[mf][nf][2], acc[mf][nf][3]);
        }
    }
}

// ---------------- split-K reduce + bias + relu + act split ----------------
__global__ void __launch_bounds__(256) reduce_kernel(
    const float* __restrict__ part,
    const float* __restrict__ bias, float bscale,
    float* __restrict__ outf,
    __nv_bfloat16* __restrict__ outh, __nv_bfloat16* __restrict__ outl)
{
    const long long i = (long long)blockIdx.x * 256 + threadIdx.x;   // float4 idx
    if (i >= 512ll * 2048 / 4) return;
    const int col = (int)((i & 511) << 2);    // 2048/4 = 512 groups per row
    const float4 p0 = *(const float4*)(part + 4 * i);
    const float4 p1 = *(const float4*)(part + 512ll * 2048 + 4 * i);
    const float4 bv = *(const float4*)(bias + col);
    float v[4] = { fmaxf(p0.x + p1.x + bscale * bv.x, 0.f),
                   fmaxf(p0.y + p1.y + bscale * bv.y, 0.f),
                   fmaxf(p0.z + p1.z + bscale * bv.z, 0.f),
                   fmaxf(p0.w + p1.w + bscale * bv.w, 0.f) };
    *(float4*)(outf + 4 * i) = make_float4(v[0], v[1], v[2], v[3]);
    __nv_bfloat16 h[4], l[4];
    #pragma unroll
    for (int e = 0; e < 4; ++e) split1(v[e], h[e], l[e]);
    *(uint2*)(outh + 4 * i) = make_uint2(pack_bf2(h[0], h[1]), pack_bf2(h[2], h[3]));
    *(uint2*)(outl + 4 * i) = make_uint2(pack_bf2(l[0], l[1]), pack_bf2(l[2], l[3]));
}

// ---------------- output layer ----------------
__global__ void __launch_bounds__(256) output_kernel(
    const float* __restrict__ a5, const float* __restrict__ a4,
    const float* __restrict__ w1, const float* __restrict__ b1,
    const float* __restrict__ w2, const float* __restrict__ b2,
    float* __restrict__ out)
{
    __shared__ float red[10][257];
    const int brow = blockIdx.x;
    const int t = threadIdx.x;
    float s[10];
    #pragma unroll
    for (int c = 0; c < 10; ++c) s[c] = 0.f;
    const float* r5 = a5 + (size_t)brow * 2048;
    const float* r4 = a4 + (size_t)brow * 2048;
    for (int n = t; n < 2048; n += 256) {
        const float x5 = r5[n], x4 = r4[n];
        #pragma unroll
        for (int c = 0; c < 10; ++c)
            s[c] += x5 * w1[c * 2048 + n] + x4 * w2[c * 2048 + n];
    }
    #pragma unroll
    for (int c = 0; c < 10; ++c) red[c][t] = s[c];
    __syncthreads();
    for (int o = 128; o > 0; o >>= 1) {
        if (t < o) {
            #pragma unroll
            for (int c = 0; c < 10; ++c) red[c][t] += red[c][t + o];
        }
        __syncthreads();
    }
    if (t < 10) out[brow * 10 + t] = red[t][0] + b1[t] + b2[t];
}

// ---------------- kernel_launch ----------------
extern "C" void kernel_launch(void* const* d_in, const int* in_sizes, int n_in,
                              void* d_out, int out_size)
{
    const float* x   = (const float*)d_in[0];
    const float* win = (const float*)d_in[1];
    const float* bin = (const float*)d_in[2];
    const float* W   = (const float*)d_in[3];
    const float* Mm  = (const float*)d_in[4];
    const float* b   = (const float*)d_in[5];
    const float* w1  = (const float*)d_in[6];
    const float* b1  = (const float*)d_in[7];
    const float* w2  = (const float*)d_in[8];
    const float* b2  = (const float*)d_in[9];
    float* out = (float*)d_out;

    float *acts, *part;
    __nv_bfloat16 *whi, *wlo, *ahi, *alo, *xhi, *xlo, *wihi, *wilo;
    cudaGetSymbolAddress((void**)&acts, g_acts);
    cudaGetSymbolAddress((void**)&part, g_part);
    cudaGetSymbolAddress((void**)&whi, g_Whi);
    cudaGetSymbolAddress((void**)&wlo, g_Wlo);
    cudaGetSymbolAddress((void**)&ahi, g_Ahi);
    cudaGetSymbolAddress((void**)&alo, g_Alo);
    cudaGetSymbolAddress((void**)&xhi, g_xhi);
    cudaGetSymbolAddress((void**)&xlo, g_xlo);
    cudaGetSymbolAddress((void**)&wihi, g_winhi);
    cudaGetSymbolAddress((void**)&wilo, g_winlo);

    cudaFuncSetAttribute(gemm_bf16_kernel,
                         cudaFuncAttributeMaxDynamicSharedMemorySize, GEMM_SMEM);

    const dim3 grid(512 / BM, 2048 / BN, 2);  // 4 x 16 x 2 = 128 CTAs
    const dim3 blk(512);
    const int rblocks = (int)((512ll * 2048 / 4 + 255) / 256);

    // (1,2) input splits
    split_pad_kernel<<<(512 * 800 + 255) / 256, 256>>>(x, 512, xhi, xlo);
    split_pad_kernel<<<(2048 * 800 + 255) / 256, 256>>>(win, 2048, wihi, wilo);

    // (3) split W*M part A: matrices 0..5 (layers 1-3)
    {
        const long long n8 = 6ll * 2048 * 2048 / 8;
        split_wm_kernel<<<(int)((n8 + 255) / 256), 256>>>(
            (const float4*)W, (const float4*)Mm, (uint4*)whi, (uint4*)wlo, n8);
    }

    // (4,5) layer 0: K=800 padded
    gemm_bf16_kernel<<<grid, blk, GEMM_SMEM>>>(
        xhi, xlo, 800, 0LL, wihi, wilo, 800, 0LL, 1, 800, part);
    reduce_kernel<<<rblocks, 256>>>(part, bin, 1.0f, acts, ahi, alo);

    // (6,7) layer 1  <- ncu capture lands on the gemm
    gemm_bf16_kernel<<<grid, blk, GEMM_SMEM>>>(
        ahi, alo, 2048, 512LL * 2048,
        whi, wlo, 2048, 2048LL * 2048, 1, 2048, part);
    reduce_kernel<<<rblocks, 256>>>(part, b, 1.0f,
        acts + 512LL * 2048, ahi + 512LL * 2048, alo + 512LL * 2048);

    // (8) split W*M part B: matrices 6..14 (layers 4-5)
    {
        const long long off = 6ll * 2048 * 2048;
        const long long n8 = 9ll * 2048 * 2048 / 8;
        split_wm_kernel<<<(int)((n8 + 255) / 256), 256>>>(
            (const float4*)(W + off), (const float4*)(Mm + off),
            (uint4*)(whi + off), (uint4*)(wlo + off), n8);
    }

    // layers 2..5
    long long idx = 1;
    for (int i = 2; i < 6; ++i) {
        gemm_bf16_kernel<<<grid, blk, GEMM_SMEM>>>(
            ahi, alo, 2048, 512LL * 2048,
            whi + idx * 2048 * 2048, wlo + idx * 2048 * 2048,
            2048, 2048LL * 2048, i, 2048, part);
        reduce_kernel<<<rblocks, 256>>>(part, b + (size_t)(i - 1) * 2048, (float)i,
            acts + (size_t)i * 512 * 2048,
            ahi + (size_t)i * 512 * 2048,
            alo + (size_t)i * 512 * 2048);
        idx += i;
    }

    // output layer
    output_kernel<<<512, 256>>>(
        acts + 5LL * 512 * 2048, acts + 4LL * 512 * 2048,
        w1, b1, w2, b2, out);
}

// round 8
// speedup vs baseline: 1.6322x; 1.3502x over previous
#include <cuda_runtime.h>
#include <cuda_fp16.h>
#include <cstdint>

// ===========================================================================
// DAG-MLP via warp-level fp16 mma.sync (m16n8k16) — compute_103-safe.
// R8 precision scheme: C = (A_hi + A_lo) * W_hi   (2 MMA streams)
//   A split into fp16 hi+lo (exact to ~2^-22); W quantized to fp16 (2^-13).
//   Legacy mma.sync tensor pipe is the ceiling (~1/3 of tcgen05 rate), so
//   fewer MMA streams == directly faster.
// ===========================================================================

#define BM 128
#define BN 128
#define BK 32
#define KSTR 40                        // padded K stride (fp16) = 80 B
#define TILE_B (128 * KSTR * 2)        // 10240 B
#define STAGE_B (3 * TILE_B)           // Ahi|Alo|Whi = 30720 B
#define STAGES 4
#define GEMM_SMEM (STAGES * STAGE_B)   // 122880 B

// ---------------- scratch (device globals; no allocations) ----------------
__device__ __half g_Whi[15ll * 2048 * 2048];   // fp16(W*M)
__device__ __half g_Ahi[6ll * 512 * 2048];     // act hi
__device__ __half g_Alo[6ll * 512 * 2048];     // act lo
__device__ __half g_xhi[512 * 800];
__device__ __half g_xlo[512 * 800];
__device__ __half g_winhi[2048 * 800];
__device__ float g_acts[6ll * 512 * 2048];
__device__ float g_part[2ll * 512 * 2048];     // split-K partials

// ---------------- helpers ----------------
static __device__ __forceinline__ uint32_t smem_u32(const void* p) {
    uint32_t r;
    asm("{ .reg .u64 t; cvta.to.shared.u64 t, %1; cvt.u32.u64 %0, t; }"
        : "=r"(r) : "l"(p));
    return r;
}

static __device__ __forceinline__ uint32_t pack_h2(__half a, __half b) {
    __half2 t; t.x = a; t.y = b;
    uint32_t u; memcpy(&u, &t, 4);
    return u;
}

static __device__ __forceinline__ void split1h(float v, __half& h, __half& l) {
    h = __float2half_rn(v);
    l = __float2half_rn(v - __half2float(h));
}

static __device__ __forceinline__ void cp16(uint32_t dst, const void* src) {
    asm volatile("cp.async.cg.shared.global [%0], [%1], 16;" :: "r"(dst), "l"(src));
}

static __device__ __forceinline__ void ldm4(uint32_t r[4], uint32_t addr) {
    asm volatile("ldmatrix.sync.aligned.m8n8.x4.shared.b16 {%0,%1,%2,%3}, [%4];"
                 : "=r"(r[0]), "=r"(r[1]), "=r"(r[2]), "=r"(r[3]) : "r"(addr));
}

static __device__ __forceinline__ void mma_fp16(
    float c[4], const uint32_t a[4], uint32_t b0, uint32_t b1) {
    asm volatile(
        "mma.sync.aligned.m16n8k16.row.col.f32.f16.f16.f32 "
        "{%0,%1,%2,%3}, {%4,%5,%6,%7}, {%8,%9}, {%0,%1,%2,%3};"
        : "+f"(c[0]), "+f"(c[1]), "+f"(c[2]), "+f"(c[3])
        : "r"(a[0]), "r"(a[1]), "r"(a[2]), "r"(a[3]), "r"(b0), "r"(b1));
}

// ---------------- pass 1: split kernels ----------------
// W*M -> fp16, 8 elems/thread (hi only; no lo needed for weights)
__global__ void __launch_bounds__(256) split_wm_kernel(
    const float4* __restrict__ W, const float4* __restrict__ M,
    uint4* __restrict__ hi, long long n8)
{
    long long i = (long long)blockIdx.x * 256 + threadIdx.x;
    if (i >= n8) return;
    const float4 w0 = W[2 * i], w1 = W[2 * i + 1];
    const float4 m0 = M[2 * i], m1 = M[2 * i + 1];
    float p[8] = { w0.x * m0.x, w0.y * m0.y, w0.z * m0.z, w0.w * m0.w,
                   w1.x * m1.x, w1.y * m1.y, w1.z * m1.z, w1.w * m1.w };
    __half h[8];
    #pragma unroll
    for (int e = 0; e < 8; ++e) h[e] = __float2half_rn(p[e]);
    hi[i] = make_uint4(pack_h2(h[0], h[1]), pack_h2(h[2], h[3]),
                       pack_h2(h[4], h[5]), pack_h2(h[6], h[7]));
}

// split + pad K 784 -> 800; lo output optional (null for weights)
__global__ void __launch_bounds__(256) split_pad_kernel(
    const float* __restrict__ src, int rows,
    __half* __restrict__ hi, __half* __restrict__ lo)
{
    long long i = (long long)blockIdx.x * 256 + threadIdx.x;
    if (i >= (long long)rows * 800) return;
    const int r = (int)(i / 800), c = (int)(i - (long long)r * 800);
    float v = (c < 784) ? src[(size_t)r * 784 + c] : 0.f;
    __half h, l;
    split1h(v, h, l);
    hi[i] = h;
    if (lo) lo[i] = l;
}

// ---------------- pass 2: GEMM layer kernel (split-K partial) --------------
__global__ void __launch_bounds__(512, 1) gemm_fp16_kernel(
    const __half* __restrict__ Ahi, const __half* __restrict__ Alo,
    int a_rs, long long a_ps,
    const __half* __restrict__ Whi,
    int w_rs, long long w_ps,
    int npred, int Kdim,
    float* __restrict__ part)
{
    extern __shared__ char smem[];
    const uint32_t sb = smem_u32(smem);
    const int tid = threadIdx.x;
    const int wid = tid >> 5;
    const int lid = tid & 31;
    const int warp_m = wid >> 2;          // 0..3
    const int warp_n = wid & 3;           // 0..3
    const int gID = lid >> 2;             // 0..7
    const int tig = lid & 3;              // 0..3
    const int m_base = blockIdx.x * BM;
    const int n_base = blockIdx.y * BN;

    const int cpp   = Kdim >> 5;
    const int total = npred * cpp;
    const int half  = (total + 1) >> 1;
    const int g_begin = blockIdx.z ? half : 0;
    const int my_n    = blockIdx.z ? (total - half) : half;

    // cp.async mapping: 512 granules of 16B per 128x32 fp16 tile
    const int grow = tid >> 2;            // 0..127
    const int gcol = (tid & 3) * 8;
    const uint32_t sdst = sb + grow * (KSTR * 2) + (tid & 3) * 16;

    const int j0   = g_begin / cpp;
    const int krem = g_begin - j0 * cpp;
    const __half* pAh = Ahi + (size_t)j0 * a_ps + (size_t)(m_base + grow) * a_rs + krem * BK + gcol;
    const __half* pAl = Alo + (size_t)j0 * a_ps + (size_t)(m_base + grow) * a_rs + krem * BK + gcol;
    const __half* pWh = Whi + (size_t)j0 * w_ps + (size_t)(n_base + grow) * w_rs + krem * BK + gcol;
    const long long a_jump = a_ps - Kdim;
    const long long w_jump = w_ps - Kdim;
    int kcnt = cpp - krem;
    uint32_t iss_off = 0;

    auto issue_adv = [&]() {
        const uint32_t d = sdst + iss_off;
        cp16(d,              pAh);
        cp16(d + TILE_B,     pAl);
        cp16(d + 2 * TILE_B, pWh);
        pAh += BK; pAl += BK; pWh += BK;
        if (--kcnt == 0) {
            kcnt = cpp;
            pAh += a_jump; pAl += a_jump; pWh += w_jump;
        }
        iss_off += STAGE_B;
        if (iss_off == STAGES * STAGE_B) iss_off = 0;
    };

    float acc[2][4][4];
    #pragma unroll
    for (int mf = 0; mf < 2; ++mf)
        #pragma unroll
        for (int nf = 0; nf < 4; ++nf)
            #pragma unroll
            for (int e = 0; e < 4; ++e) acc[mf][nf][e] = 0.f;

    const int lrow  = lid & 15;
    const int khalf = (lid >> 4) * 8;
    const uint32_t aoff  = ((warp_m * 32 + lrow) * KSTR + khalf) * 2;
    const uint32_t boff0 = ((warp_n * 32 + lrow) * KSTR + khalf) * 2 + 2 * TILE_B;
    const uint32_t boff1 = boff0 + 16 * KSTR * 2;

    #pragma unroll
    for (int p = 0; p < STAGES - 1; ++p) {
        if (p < my_n) issue_adv();
        asm volatile("cp.async.commit_group;");
    }

    uint32_t rd_off = 0;
    for (int g = 0; g < my_n; ++g) {
        asm volatile("cp.async.wait_group %0;" :: "n"(STAGES - 2));
        __syncthreads();
        if (g + STAGES - 1 < my_n) issue_adv();
        asm volatile("cp.async.commit_group;");

        const uint32_t st = sb + rd_off;
        rd_off += STAGE_B;
        if (rd_off == STAGES * STAGE_B) rd_off = 0;

        #pragma unroll
        for (int ks = 0; ks < 2; ++ks) {
            const uint32_t ko = ks * 32;
            uint32_t ah0[4], ah1[4], al0[4], al1[4], bh0[4], bh1[4];
            ldm4(bh0, st + boff0 + ko);
            ldm4(bh1, st + boff1 + ko);
            ldm4(ah0, st + aoff + ko);
            ldm4(ah1, st + aoff + 16 * KSTR * 2 + ko);
            ldm4(al0, st + aoff + TILE_B + ko);
            ldm4(al1, st + aoff + TILE_B + 16 * KSTR * 2 + ko);
            // hh stream (8 independent accs)
            mma_fp16(acc[0][0], ah0, bh0[0], bh0[2]);
            mma_fp16(acc[0][1], ah0, bh0[1], bh0[3]);
            mma_fp16(acc[0][2], ah0, bh1[0], bh1[2]);
            mma_fp16(acc[0][3], ah0, bh1[1], bh1[3]);
            mma_fp16(acc[1][0], ah1, bh0[0], bh0[2]);
            mma_fp16(acc[1][1], ah1, bh0[1], bh0[3]);
            mma_fp16(acc[1][2], ah1, bh1[0], bh1[2]);
            mma_fp16(acc[1][3], ah1, bh1[1], bh1[3]);
            // lh stream
            mma_fp16(acc[0][0], al0, bh0[0], bh0[2]);
            mma_fp16(acc[0][1], al0, bh0[1], bh0[3]);
            mma_fp16(acc[0][2], al0, bh1[0], bh1[2]);
            mma_fp16(acc[0][3], al0, bh1[1], bh1[3]);
            mma_fp16(acc[1][0], al1, bh0[0], bh0[2]);
            mma_fp16(acc[1][1], al1, bh0[1], bh0[3]);
            mma_fp16(acc[1][2], al1, bh1[0], bh1[2]);
            mma_fp16(acc[1][3], al1, bh1[1], bh1[3]);
        }
    }

    float* pz = part + (size_t)blockIdx.z * 512 * 2048;
    #pragma unroll
    for (int mf = 0; mf < 2; ++mf) {
        const int r0 = m_base + warp_m * 32 + mf * 16 + gID;
        #pragma unroll
        for (int nf = 0; nf < 4; ++nf) {
            const int c0 = n_base + warp_n * 32 + nf * 8 + 2 * tig;
            *(float2*)(pz + (size_t)r0 * 2048 + c0)       = make_float2(acc[mf][nf][0], acc[mf][nf][1]);
            *(float2*)(pz + (size_t)(r0 + 8) * 2048 + c0) = make_float2(acc[mf][nf][2], acc[mf][nf][3]);
        }
    }
}

// ---------------- split-K reduce + bias + relu + act split ----------------
__global__ void __launch_bounds__(256) reduce_kernel(
    const float* __restrict__ part,
    const float* __restrict__ bias, float bscale,
    float* __restrict__ outf,
    __half* __restrict__ outh, __half* __restrict__ outl)
{
    const long long i = (long long)blockIdx.x * 256 + threadIdx.x;   // float4 idx
    if (i >= 512ll * 2048 / 4) return;
    const int col = (int)((i & 511) << 2);
    const float4 p0 = *(const float4*)(part + 4 * i);
    const float4 p1 = *(const float4*)(part + 512ll * 2048 + 4 * i);
    const float4 bv = *(const float4*)(bias + col);
    float v[4] = { fmaxf(p0.x + p1.x + bscale * bv.x, 0.f),
                   fmaxf(p0.y + p1.y + bscale * bv.y, 0.f),
                   fmaxf(p0.z + p1.z + bscale * bv.z, 0.f),
                   fmaxf(p0.w + p1.w + bscale * bv.w, 0.f) };
    *(float4*)(outf + 4 * i) = make_float4(v[0], v[1], v[2], v[3]);
    __half h[4], l[4];
    #pragma unroll
    for (int e = 0; e < 4; ++e) split1h(v[e], h[e], l[e]);
    *(uint2*)(outh + 4 * i) = make_uint2(pack_h2(h[0], h[1]), pack_h2(h[2], h[3]));
    *(uint2*)(outl + 4 * i) = make_uint2(pack_h2(l[0], l[1]), pack_h2(l[2], l[3]));
}

// ---------------- output layer ----------------
__global__ void __launch_bounds__(256) output_kernel(
    const float* __restrict__ a5, const float* __restrict__ a4,
    const float* __restrict__ w1, const float* __restrict__ b1,
    const float* __restrict__ w2, const float* __restrict__ b2,
    float* __restrict__ out)
{
    __shared__ float red[10][257];
    const int brow = blockIdx.x;
    const int t = threadIdx.x;
    float s[10];
    #pragma unroll
    for (int c = 0; c < 10; ++c) s[c] = 0.f;
    const float* r5 = a5 + (size_t)brow * 2048;
    const float* r4 = a4 + (size_t)brow * 2048;
    for (int n = t; n < 2048; n += 256) {
        const float x5 = r5[n], x4 = r4[n];
        #pragma unroll
        for (int c = 0; c < 10; ++c)
            s[c] += x5 * w1[c * 2048 + n] + x4 * w2[c * 2048 + n];
    }
    #pragma unroll
    for (int c = 0; c < 10; ++c) red[c][t] = s[c];
    __syncthreads();
    for (int o = 128; o > 0; o >>= 1) {
        if (t < o) {
            #pragma unroll
            for (int c = 0; c < 10; ++c) red[c][t] += red[c][t + o];
        }
        __syncthreads();
    }
    if (t < 10) out[brow * 10 + t] = red[t][0] + b1[t] + b2[t];
}

// ---------------- kernel_launch ----------------
extern "C" void kernel_launch(void* const* d_in, const int* in_sizes, int n_in,
                              void* d_out, int out_size)
{
    const float* x   = (const float*)d_in[0];
    const float* win = (const float*)d_in[1];
    const float* bin = (const float*)d_in[2];
    const float* W   = (const float*)d_in[3];
    const float* Mm  = (const float*)d_in[4];
    const float* b   = (const float*)d_in[5];
    const float* w1  = (const float*)d_in[6];
    const float* b1  = (const float*)d_in[7];
    const float* w2  = (const float*)d_in[8];
    const float* b2  = (const float*)d_in[9];
    float* out = (float*)d_out;

    float *acts, *part;
    __half *whi, *ahi, *alo, *xhi, *xlo, *wihi;
    cudaGetSymbolAddress((void**)&acts, g_acts);
    cudaGetSymbolAddress((void**)&part, g_part);
    cudaGetSymbolAddress((void**)&whi, g_Whi);
    cudaGetSymbolAddress((void**)&ahi, g_Ahi);
    cudaGetSymbolAddress((void**)&alo, g_Alo);
    cudaGetSymbolAddress((void**)&xhi, g_xhi);
    cudaGetSymbolAddress((void**)&xlo, g_xlo);
    cudaGetSymbolAddress((void**)&wihi, g_winhi);

    cudaFuncSetAttribute(gemm_fp16_kernel,
                         cudaFuncAttributeMaxDynamicSharedMemorySize, GEMM_SMEM);

    const dim3 grid(512 / BM, 2048 / BN, 2);  // 4 x 16 x 2 = 128 CTAs
    const dim3 blk(512);
    const int rblocks = (int)((512ll * 2048 / 4 + 255) / 256);

    // (1,2) input splits (x: hi+lo, w_in: hi only)
    split_pad_kernel<<<(512 * 800 + 255) / 256, 256>>>(x, 512, xhi, xlo);
    split_pad_kernel<<<(2048 * 800 + 255) / 256, 256>>>(win, 2048, wihi, nullptr);

    // (3) split W*M -> fp16 (all 15 matrices)
    {
        const long long n8 = 15ll * 2048 * 2048 / 8;
        split_wm_kernel<<<(int)((n8 + 255) / 256), 256>>>(
            (const float4*)W, (const float4*)Mm, (uint4*)whi, n8);
    }

    // (4,5) layer 0: K=800 padded
    gemm_fp16_kernel<<<grid, blk, GEMM_SMEM>>>(
        xhi, xlo, 800, 0LL, wihi, 800, 0LL, 1, 800, part);
    reduce_kernel<<<rblocks, 256>>>(part, bin, 1.0f, acts, ahi, alo);

    // (6,7) layer 1  <- ncu capture lands on the gemm
    gemm_fp16_kernel<<<grid, blk, GEMM_SMEM>>>(
        ahi, alo, 2048, 512LL * 2048,
        whi, 2048, 2048LL * 2048, 1, 2048, part);
    reduce_kernel<<<rblocks, 256>>>(part, b, 1.0f,
        acts + 512LL * 2048, ahi + 512LL * 2048, alo + 512LL * 2048);

    // layers 2..5
    long long idx = 1;
    for (int i = 2; i < 6; ++i) {
        gemm_fp16_kernel<<<grid, blk, GEMM_SMEM>>>(
            ahi, alo, 2048, 512LL * 2048,
            whi + idx * 2048 * 2048,
            2048, 2048LL * 2048, i, 2048, part);
        reduce_kernel<<<rblocks, 256>>>(part, b + (size_t)(i - 1) * 2048, (float)i,
            acts + (size_t)i * 512 * 2048,
            ahi + (size_t)i * 512 * 2048,
            alo + (size_t)i * 512 * 2048);
        idx += i;
    }

    // output layer
    output_kernel<<<512, 256>>>(
        acts + 5LL * 512 * 2048, acts + 4LL * 512 * 2048,
        w1, b1, w2, b2, out);
}

// round 9
// speedup vs baseline: 2.3895x; 1.4639x over previous
#include <cuda_runtime.h>
#include <cuda_fp16.h>
#include <cstdint>

// ===========================================================================
// DAG-MLP via warp-level fp16 mma.sync (m16n8k16) — compute_103-safe.
// R9 precision scheme: C = A_hi * W_hi  (single MMA stream)
//   Both A and W quantized to fp16 (u=2^-11). Calibrated error model:
//   ~2.0e-4 per quantization source, ~12 sources -> ~7e-4 < 1e-3.
//   Legacy mma.sync tensor pipe is the binder; halving MMA work halves GEMM.
// ===========================================================================

#define BM 128
#define BN 128
#define BK 32
#define KSTR 40                        // padded K stride (fp16) = 80 B
#define TILE_B (128 * KSTR * 2)        // 10240 B
#define STAGE_B (2 * TILE_B)           // Ahi|Whi = 20480 B
#define STAGES 5
#define GEMM_SMEM (STAGES * STAGE_B)   // 102400 B

// ---------------- scratch (device globals; no allocations) ----------------
__device__ __half g_Whi[15ll * 2048 * 2048];   // fp16(W*M)
__device__ __half g_Ahi[6ll * 512 * 2048];     // fp16 acts
__device__ __half g_xhi[512 * 800];
__device__ __half g_winhi[2048 * 800];
__device__ float g_acts[6ll * 512 * 2048];
__device__ float g_part[2ll * 512 * 2048];     // split-K partials

// ---------------- helpers ----------------
static __device__ __forceinline__ uint32_t smem_u32(const void* p) {
    uint32_t r;
    asm("{ .reg .u64 t; cvta.to.shared.u64 t, %1; cvt.u32.u64 %0, t; }"
        : "=r"(r) : "l"(p));
    return r;
}

static __device__ __forceinline__ uint32_t pack_h2(__half a, __half b) {
    __half2 t; t.x = a; t.y = b;
    uint32_t u; memcpy(&u, &t, 4);
    return u;
}

static __device__ __forceinline__ void cp16(uint32_t dst, const void* src) {
    asm volatile("cp.async.cg.shared.global [%0], [%1], 16;" :: "r"(dst), "l"(src));
}

static __device__ __forceinline__ void ldm4(uint32_t r[4], uint32_t addr) {
    asm volatile("ldmatrix.sync.aligned.m8n8.x4.shared.b16 {%0,%1,%2,%3}, [%4];"
                 : "=r"(r[0]), "=r"(r[1]), "=r"(r[2]), "=r"(r[3]) : "r"(addr));
}

static __device__ __forceinline__ void mma_fp16(
    float c[4], const uint32_t a[4], uint32_t b0, uint32_t b1) {
    asm volatile(
        "mma.sync.aligned.m16n8k16.row.col.f32.f16.f16.f32 "
        "{%0,%1,%2,%3}, {%4,%5,%6,%7}, {%8,%9}, {%0,%1,%2,%3};"
        : "+f"(c[0]), "+f"(c[1]), "+f"(c[2]), "+f"(c[3])
        : "r"(a[0]), "r"(a[1]), "r"(a[2]), "r"(a[3]), "r"(b0), "r"(b1));
}

// ---------------- pass 1: split kernels ----------------
__global__ void __launch_bounds__(256) split_wm_kernel(
    const float4* __restrict__ W, const float4* __restrict__ M,
    uint4* __restrict__ hi, long long n8)
{
    long long i = (long long)blockIdx.x * 256 + threadIdx.x;
    if (i >= n8) return;
    const float4 w0 = W[2 * i], w1 = W[2 * i + 1];
    const float4 m0 = M[2 * i], m1 = M[2 * i + 1];
    float p[8] = { w0.x * m0.x, w0.y * m0.y, w0.z * m0.z, w0.w * m0.w,
                   w1.x * m1.x, w1.y * m1.y, w1.z * m1.z, w1.w * m1.w };
    __half h[8];
    #pragma unroll
    for (int e = 0; e < 8; ++e) h[e] = __float2half_rn(p[e]);
    hi[i] = make_uint4(pack_h2(h[0], h[1]), pack_h2(h[2], h[3]),
                       pack_h2(h[4], h[5]), pack_h2(h[6], h[7]));
}

// fp32 -> fp16 with K pad 784 -> 800
__global__ void __launch_bounds__(256) split_pad_kernel(
    const float* __restrict__ src, int rows, __half* __restrict__ hi)
{
    long long i = (long long)blockIdx.x * 256 + threadIdx.x;
    if (i >= (long long)rows * 800) return;
    const int r = (int)(i / 800), c = (int)(i - (long long)r * 800);
    float v = (c < 784) ? src[(size_t)r * 784 + c] : 0.f;
    hi[i] = __float2half_rn(v);
}

// ---------------- pass 2: GEMM layer kernel (split-K partial) --------------
__global__ void __launch_bounds__(512, 1) gemm_fp16_kernel(
    const __half* __restrict__ Ahi,
    int a_rs, long long a_ps,
    const __half* __restrict__ Whi,
    int w_rs, long long w_ps,
    int npred, int Kdim,
    float* __restrict__ part)
{
    extern __shared__ char smem[];
    const uint32_t sb = smem_u32(smem);
    const int tid = threadIdx.x;
    const int wid = tid >> 5;
    const int lid = tid & 31;
    const int warp_m = wid >> 2;          // 0..3
    const int warp_n = wid & 3;           // 0..3
    const int gID = lid >> 2;             // 0..7
    const int tig = lid & 3;              // 0..3
    const int m_base = blockIdx.x * BM;
    const int n_base = blockIdx.y * BN;

    const int cpp   = Kdim >> 5;
    const int total = npred * cpp;
    const int half  = (total + 1) >> 1;
    const int g_begin = blockIdx.z ? half : 0;
    const int my_n    = blockIdx.z ? (total - half) : half;

    // cp.async mapping: 512 granules of 16B per 128x32 fp16 tile
    const int grow = tid >> 2;            // 0..127
    const int gcol = (tid & 3) * 8;
    const uint32_t sdst = sb + grow * (KSTR * 2) + (tid & 3) * 16;

    const int j0   = g_begin / cpp;
    const int krem = g_begin - j0 * cpp;
    const __half* pAh = Ahi + (size_t)j0 * a_ps + (size_t)(m_base + grow) * a_rs + krem * BK + gcol;
    const __half* pWh = Whi + (size_t)j0 * w_ps + (size_t)(n_base + grow) * w_rs + krem * BK + gcol;
    const long long a_jump = a_ps - Kdim;
    const long long w_jump = w_ps - Kdim;
    int kcnt = cpp - krem;
    uint32_t iss_off = 0;

    auto issue_adv = [&]() {
        const uint32_t d = sdst + iss_off;
        cp16(d,          pAh);
        cp16(d + TILE_B, pWh);
        pAh += BK; pWh += BK;
        if (--kcnt == 0) {
            kcnt = cpp;
            pAh += a_jump; pWh += w_jump;
        }
        iss_off += STAGE_B;
        if (iss_off == STAGES * STAGE_B) iss_off = 0;
    };

    float acc[2][4][4];
    #pragma unroll
    for (int mf = 0; mf < 2; ++mf)
        #pragma unroll
        for (int nf = 0; nf < 4; ++nf)
            #pragma unroll
            for (int e = 0; e < 4; ++e) acc[mf][nf][e] = 0.f;

    const int lrow  = lid & 15;
    const int khalf = (lid >> 4) * 8;
    const uint32_t aoff  = ((warp_m * 32 + lrow) * KSTR + khalf) * 2;
    const uint32_t boff0 = ((warp_n * 32 + lrow) * KSTR + khalf) * 2 + TILE_B;
    const uint32_t boff1 = boff0 + 16 * KSTR * 2;

    #pragma unroll
    for (int p = 0; p < STAGES - 1; ++p) {
        if (p < my_n) issue_adv();
        asm volatile("cp.async.commit_group;");
    }

    uint32_t rd_off = 0;
    for (int g = 0; g < my_n; ++g) {
        asm volatile("cp.async.wait_group %0;" :: "n"(STAGES - 2));
        __syncthreads();
        if (g + STAGES - 1 < my_n) issue_adv();
        asm volatile("cp.async.commit_group;");

        const uint32_t st = sb + rd_off;
        rd_off += STAGE_B;
        if (rd_off == STAGES * STAGE_B) rd_off = 0;

        #pragma unroll
        for (int ks = 0; ks < 2; ++ks) {
            const uint32_t ko = ks * 32;
            uint32_t ah0[4], ah1[4], bh0[4], bh1[4];
            ldm4(bh0, st + boff0 + ko);
            ldm4(bh1, st + boff1 + ko);
            ldm4(ah0, st + aoff + ko);
            ldm4(ah1, st + aoff + 16 * KSTR * 2 + ko);
            mma_fp16(acc[0][0], ah0, bh0[0], bh0[2]);
            mma_fp16(acc[0][1], ah0, bh0[1], bh0[3]);
            mma_fp16(acc[0][2], ah0, bh1[0], bh1[2]);
            mma_fp16(acc[0][3], ah0, bh1[1], bh1[3]);
            mma_fp16(acc[1][0], ah1, bh0[0], bh0[2]);
            mma_fp16(acc[1][1], ah1, bh0[1], bh0[3]);
            mma_fp16(acc[1][2], ah1, bh1[0], bh1[2]);
            mma_fp16(acc[1][3], ah1, bh1[1], bh1[3]);
        }
    }

    float* pz = part + (size_t)blockIdx.z * 512 * 2048;
    #pragma unroll
    for (int mf = 0; mf < 2; ++mf) {
        const int r0 = m_base + warp_m * 32 + mf * 16 + gID;
        #pragma unroll
        for (int nf = 0; nf < 4; ++nf) {
            const int c0 = n_base + warp_n * 32 + nf * 8 + 2 * tig;
            *(float2*)(pz + (size_t)r0 * 2048 + c0)       = make_float2(acc[mf][nf][0], acc[mf][nf][1]);
            *(float2*)(pz + (size_t)(r0 + 8) * 2048 + c0) = make_float2(acc[mf][nf][2], acc[mf][nf][3]);
        }
    }
}

// ---------------- split-K reduce + bias + relu + act quantize --------------
__global__ void __launch_bounds__(256) reduce_kernel(
    const float* __restrict__ part,
    const float* __restrict__ bias, float bscale,
    float* __restrict__ outf, __half* __restrict__ outh)
{
    const long long i = (long long)blockIdx.x * 256 + threadIdx.x;   // float4 idx
    if (i >= 512ll * 2048 / 4) return;
    const int col = (int)((i & 511) << 2);
    const float4 p0 = *(const float4*)(part + 4 * i);
    const float4 p1 = *(const float4*)(part + 512ll * 2048 + 4 * i);
    const float4 bv = *(const float4*)(bias + col);
    float v[4] = { fmaxf(p0.x + p1.x + bscale * bv.x, 0.f),
                   fmaxf(p0.y + p1.y + bscale * bv.y, 0.f),
                   fmaxf(p0.z + p1.z + bscale * bv.z, 0.f),
                   fmaxf(p0.w + p1.w + bscale * bv.w, 0.f) };
    *(float4*)(outf + 4 * i) = make_float4(v[0], v[1], v[2], v[3]);
    __half h[4];
    #pragma unroll
    for (int e = 0; e < 4; ++e) h[e] = __float2half_rn(v[e]);
    *(uint2*)(outh + 4 * i) = make_uint2(pack_h2(h[0], h[1]), pack_h2(h[2], h[3]));
}

// ---------------- output layer ----------------
__global__ void __launch_bounds__(256) output_kernel(
    const float* __restrict__ a5, const float* __restrict__ a4,
    const float* __restrict__ w1, const float* __restrict__ b1,
    const float* __restrict__ w2, const float* __restrict__ b2,
    float* __restrict__ out)
{
    __shared__ float red[10][257];
    const int brow = blockIdx.x;
    const int t = threadIdx.x;
    float s[10];
    #pragma unroll
    for (int c = 0; c < 10; ++c) s[c] = 0.f;
    const float* r5 = a5 + (size_t)brow * 2048;
    const float* r4 = a4 + (size_t)brow * 2048;
    for (int n = t; n < 2048; n += 256) {
        const float x5 = r5[n], x4 = r4[n];
        #pragma unroll
        for (int c = 0; c < 10; ++c)
            s[c] += x5 * w1[c * 2048 + n] + x4 * w2[c * 2048 + n];
    }
    #pragma unroll
    for (int c = 0; c < 10; ++c) red[c][t] = s[c];
    __syncthreads();
    for (int o = 128; o > 0; o >>= 1) {
        if (t < o) {
            #pragma unroll
            for (int c = 0; c < 10; ++c) red[c][t] += red[c][t + o];
        }
        __syncthreads();
    }
    if (t < 10) out[brow * 10 + t] = red[t][0] + b1[t] + b2[t];
}

// ---------------- kernel_launch ----------------
extern "C" void kernel_launch(void* const* d_in, const int* in_sizes, int n_in,
                              void* d_out, int out_size)
{
    const float* x   = (const float*)d_in[0];
    const float* win = (const float*)d_in[1];
    const float* bin = (const float*)d_in[2];
    const float* W   = (const float*)d_in[3];
    const float* Mm  = (const float*)d_in[4];
    const float* b   = (const float*)d_in[5];
    const float* w1  = (const float*)d_in[6];
    const float* b1  = (const float*)d_in[7];
    const float* w2  = (const float*)d_in[8];
    const float* b2  = (const float*)d_in[9];
    float* out = (float*)d_out;

    float *acts, *part;
    __half *whi, *ahi, *xhi, *wihi;
    cudaGetSymbolAddress((void**)&acts, g_acts);
    cudaGetSymbolAddress((void**)&part, g_part);
    cudaGetSymbolAddress((void**)&whi, g_Whi);
    cudaGetSymbolAddress((void**)&ahi, g_Ahi);
    cudaGetSymbolAddress((void**)&xhi, g_xhi);
    cudaGetSymbolAddress((void**)&wihi, g_winhi);

    cudaFuncSetAttribute(gemm_fp16_kernel,
                         cudaFuncAttributeMaxDynamicSharedMemorySize, GEMM_SMEM);

    const dim3 grid(512 / BM, 2048 / BN, 2);  // 4 x 16 x 2 = 128 CTAs
    const dim3 blk(512);
    const int rblocks = (int)((512ll * 2048 / 4 + 255) / 256);

    // (1,2) input quantize (x, w_in), K padded to 800
    split_pad_kernel<<<(512 * 800 + 255) / 256, 256>>>(x, 512, xhi);
    split_pad_kernel<<<(2048 * 800 + 255) / 256, 256>>>(win, 2048, wihi);

    // (3) quantize W*M -> fp16 (all 15 matrices)
    {
        const long long n8 = 15ll * 2048 * 2048 / 8;
        split_wm_kernel<<<(int)((n8 + 255) / 256), 256>>>(
            (const float4*)W, (const float4*)Mm, (uint4*)whi, n8);
    }

    // (4,5) layer 0: K=800 padded
    gemm_fp16_kernel<<<grid, blk, GEMM_SMEM>>>(
        xhi, 800, 0LL, wihi, 800, 0LL, 1, 800, part);
    reduce_kernel<<<rblocks, 256>>>(part, bin, 1.0f, acts, ahi);

    // (6,7) layer 1  <- ncu capture lands on the gemm
    gemm_fp16_kernel<<<grid, blk, GEMM_SMEM>>>(
        ahi, 2048, 512LL * 2048,
        whi, 2048, 2048LL * 2048, 1, 2048, part);
    reduce_kernel<<<rblocks, 256>>>(part, b, 1.0f,
        acts + 512LL * 2048, ahi + 512LL * 2048);

    // layers 2..5
    long long idx = 1;
    for (int i = 2; i < 6; ++i) {
        gemm_fp16_kernel<<<grid, blk, GEMM_SMEM>>>(
            ahi, 2048, 512LL * 2048,
            whi + idx * 2048 * 2048,
            2048, 2048LL * 2048, i, 2048, part);
        reduce_kernel<<<rblocks, 256>>>(part, b + (size_t)(i - 1) * 2048, (float)i,
            acts + (size_t)i * 512 * 2048,
            ahi + (size_t)i * 512 * 2048);
        idx += i;
    }

    // output layer
    output_kernel<<<512, 256>>>(
        acts + 5LL * 512 * 2048, acts + 4LL * 512 * 2048,
        w1, b1, w2, b2, out);
}